// round 1
// baseline (speedup 1.0000x reference)
#include <cuda_runtime.h>
#include <cuda_bf16.h>

// Problem constants (fixed shapes from reference setup_inputs)
#define NB 16    // batch
#define C_IN 64
#define H_IN 128
#define W_IN 128
#define K_OUT 128
#define P_OUT 126
#define Q_OUT 126

// Block tiling
#define TH 8     // output rows per block
#define TW 32    // output cols per block
#define TK 32    // output channels per block
#define IN_ROWS (TH + 2)      // 10
#define IN_COLS (TW + 2)      // 34
#define IN_STRIDE 35          // padded to kill bank conflicts
#define NTHREADS 256

__global__ __launch_bounds__(NTHREADS, 4)
void conv2d_direct_f32_kernel(const float* __restrict__ data,
                              const float* __restrict__ wts,
                              float* __restrict__ out)
{
    __shared__ float s_in[IN_ROWS * IN_STRIDE];  // 10*35*4 = 1400 B
    __shared__ float s_w[TK * 9];                // 32*9*4  = 1152 B

    const int bx = blockIdx.x;            // col tile  [0,4)
    const int by = blockIdx.y;            // row tile  [0,16)
    const int bz = blockIdx.z;            // batch*4 + ktile
    const int n  = bz >> 2;
    const int k0 = (bz & 3) * TK;
    const int x0 = bx * TW;
    const int y0 = by * TH;

    const int tid = threadIdx.x;
    const int kg  = tid >> 6;             // [0,4)  channel group of 8
    const int y   = (tid >> 3) & 7;       // [0,8)  row within tile
    const int xg  = tid & 7;              // [0,8)  column group of 4

    float acc[8][4];
    #pragma unroll
    for (int k = 0; k < 8; k++)
        #pragma unroll
        for (int j = 0; j < 4; j++)
            acc[k][j] = 0.0f;

    const float* inb = data + (size_t)n * C_IN * H_IN * W_IN;

    for (int c = 0; c < C_IN; c++) {
        // ---- load input tile for channel c (with zero-pad at image edge) ----
        const float* ic = inb + (size_t)c * H_IN * W_IN;
        #pragma unroll
        for (int i = tid; i < IN_ROWS * IN_COLS; i += NTHREADS) {
            int rr = i / IN_COLS;
            int cc = i - rr * IN_COLS;
            int gy = y0 + rr;
            int gx = x0 + cc;
            float v = (gy < H_IN && gx < W_IN) ? ic[gy * W_IN + gx] : 0.0f;
            s_in[rr * IN_STRIDE + cc] = v;
        }
        // ---- load weights for k0..k0+31, channel c ----
        const float* wc = wts + (size_t)k0 * C_IN * 9 + (size_t)c * 9;
        #pragma unroll
        for (int i = tid; i < TK * 9; i += NTHREADS) {
            int kk = i / 9;
            int rs = i - kk * 9;
            s_w[i] = wc[(size_t)kk * C_IN * 9 + rs];
        }
        __syncthreads();

        // ---- compute: per thread 8 channels x 4 columns ----
        #pragma unroll
        for (int r = 0; r < 3; r++) {
            float xrow[6];
            #pragma unroll
            for (int j = 0; j < 6; j++)
                xrow[j] = s_in[(y + r) * IN_STRIDE + xg * 4 + j];
            #pragma unroll
            for (int s = 0; s < 3; s++) {
                float wv[8];
                #pragma unroll
                for (int k = 0; k < 8; k++)
                    wv[k] = s_w[(kg * 8 + k) * 9 + r * 3 + s];  // warp-uniform -> broadcast
                #pragma unroll
                for (int k = 0; k < 8; k++)
                    #pragma unroll
                    for (int j = 0; j < 4; j++)
                        acc[k][j] = fmaf(wv[k], xrow[s + j], acc[k][j]);
            }
        }
        __syncthreads();
    }

    // ---- store ----
    const int oy = y0 + y;
    const int ox = x0 + xg * 4;
    if (oy < P_OUT) {
        #pragma unroll
        for (int k = 0; k < 8; k++) {
            int ko = k0 + kg * 8 + k;
            float* op = out + (((size_t)n * K_OUT + ko) * P_OUT + oy) * (size_t)Q_OUT + ox;
            #pragma unroll
            for (int j = 0; j < 4; j++)
                if (ox + j < Q_OUT) op[j] = acc[k][j];
        }
    }
}

extern "C" void kernel_launch(void* const* d_in, const int* in_sizes, int n_in,
                              void* d_out, int out_size)
{
    const float* data = (const float*)d_in[0];   // [16,64,128,128]
    const float* wts  = (const float*)d_in[1];   // [128,64,3,3]
    float* out        = (float*)d_out;           // [16,128,126,126]

    dim3 grid((Q_OUT + TW - 1) / TW,             // 4
              (P_OUT + TH - 1) / TH,             // 16
              NB * (K_OUT / TK));                // 64
    conv2d_direct_f32_kernel<<<grid, NTHREADS>>>(data, wts, out);
}

// round 5
// speedup vs baseline: 7.3388x; 7.3388x over previous
#include <cuda_runtime.h>
#include <cuda_fp16.h>
#include <cstdint>

// Problem shapes
#define NB    16
#define C_IN  64
#define H_IN  128
#define W_IN  128
#define K_OUT 128
#define P_OUT 126
#define Q_OUT 126
#define PQ    (P_OUT * Q_OUT)

// ---------------- scratch (device globals: allocation-free) ----------------
// +1024 halves of pad: q+s window reads up to w=129 on the last image row.
__device__ __align__(1024) __half g_input_h[(size_t)NB * H_IN * W_IN * C_IN + 1024]; // NHWC fp16
__device__ __align__(1024) __half g_w9[9 * K_OUT * C_IN];                             // [rs][k][c]

// ---------------- PTX helpers (all sm_80-level: works on compute_103) ----------------
__device__ __forceinline__ uint32_t smem_u32(const void* p) {
    uint32_t a;
    asm("{ .reg .u64 t; cvta.to.shared.u64 t, %1; cvt.u32.u64 %0, t; }" : "=r"(a) : "l"(p));
    return a;
}

#define CP_ASYNC16(dst, src) \
    asm volatile("cp.async.cg.shared.global [%0], [%1], 16;\n" :: "r"(dst), "l"(src) : "memory")
#define CP_COMMIT() asm volatile("cp.async.commit_group;\n" ::: "memory")
#define CP_WAIT2()  asm volatile("cp.async.wait_group 2;\n" ::: "memory")

#define LDSM_X4(R, addr) \
    asm volatile("ldmatrix.sync.aligned.m8n8.x4.shared.b16 {%0,%1,%2,%3}, [%4];\n" \
        : "=r"((R)[0]), "=r"((R)[1]), "=r"((R)[2]), "=r"((R)[3]) : "r"(addr))

#define MMA16816(C, A, B0, B1) \
    asm volatile("mma.sync.aligned.m16n8k16.row.col.f32.f16.f16.f32 " \
        "{%0,%1,%2,%3}, {%4,%5,%6,%7}, {%8,%9}, {%0,%1,%2,%3};\n" \
        : "+f"((C)[0]), "+f"((C)[1]), "+f"((C)[2]), "+f"((C)[3]) \
        : "r"((A)[0]), "r"((A)[1]), "r"((A)[2]), "r"((A)[3]), "r"(B0), "r"(B1))

// ---------------- prologue kernels ----------------
// NCHW f32 -> NHWC fp16 (tiled transpose through smem)
__global__ void convert_input_kernel(const float* __restrict__ data) {
    __shared__ float s[64 * 33];
    const int w0 = blockIdx.x * 32, h = blockIdx.y, n = blockIdx.z;
    const int tid = threadIdx.x;
#pragma unroll
    for (int it = 0; it < 8; it++) {
        int i = it * 256 + tid;
        int c = i >> 5, w = i & 31;
        s[c * 33 + w] = data[(((size_t)n * C_IN + c) * H_IN + h) * W_IN + w0 + w];
    }
    __syncthreads();
    __half2* gp = (__half2*)g_input_h;
#pragma unroll
    for (int it = 0; it < 4; it++) {
        int i = it * 256 + tid;
        int w = i >> 5, cp = i & 31;
        float lo = s[(2 * cp) * 33 + w];
        float hi = s[(2 * cp + 1) * 33 + w];
        gp[(((size_t)n * H_IN + h) * W_IN + w0 + w) * 32 + cp] = __floats2half2_rn(lo, hi);
    }
}

// W[k,c,r,s] f32 -> g_w9[rs][k][c] fp16
__global__ void convert_weights_kernel(const float* __restrict__ w) {
    int i = blockIdx.x * 256 + threadIdx.x;
    if (i >= 9 * K_OUT * C_IN) return;
    int rs = i / (K_OUT * C_IN);
    int rem = i - rs * (K_OUT * C_IN);
    int k = rem >> 6, c = rem & 63;
    int r = rs / 3, s = rs - r * 3;
    g_w9[i] = __float2half(w[((k * C_IN + c) * 3 + r) * 3 + s]);
}

// ---------------- main mma.sync conv kernel ----------------
#define NTHREADS 256
#define NCTA 144
#define TILES_TOTAL (NB * P_OUT)      // 2016 = 14 * 144
#define NSTAGES 42                    // 14 tiles * 3 r-stages
#define W_SLOT 16384                  // 128 rows(k) x 128B(64 halves)
#define IN_ROWS 130
#define IN_SLOT (IN_ROWS * 128)       // 16640 B
#define SM_IN_OFF (9 * W_SLOT)        // 147456
#define SM_TOTAL (SM_IN_OFF + 4 * IN_SLOT)  // 214016 B

__global__ void __launch_bounds__(NTHREADS, 1)
conv_mma_kernel(float* __restrict__ out)
{
    extern __shared__ char smem[];
    const uint32_t sb = smem_u32(smem);
    const int tid  = threadIdx.x;
    const int lane = tid & 31;
    const int wid  = tid >> 5;
    const int k0w  = (wid & 1) * 64;   // warp's out-channel base (GEMM m)
    const int q0w  = (wid >> 1) * 32;  // warp's q base           (GEMM n)

    // ---- issue resident weight loads (9 x 128 x 128B, XOR-swizzled rows) ----
    {
#pragma unroll 4
        for (int it = 0; it < 36; it++) {
            int i   = it * 256 + tid;            // 16B chunk index, [0, 9216)
            int ch  = i & 7;
            int row = (i >> 3) & 127;
            int rs  = i >> 10;
            uint32_t dst = sb + rs * W_SLOT + row * 128 + ((ch ^ (row & 7)) << 4);
            CP_ASYNC16(dst, g_w9 + (size_t)i * 8);
        }
    }

    // ---- input stage loader: stage s -> tile (s/3), image row p + (s%3) ----
    auto issue_stage = [&](int s) {
        int ti = s / 3;
        int r  = s - ti * 3;
        int t  = ti * NCTA + blockIdx.x;         // tile id (contiguous across CTAs per wave)
        int n  = t / P_OUT, p = t - n * P_OUT;
        const __half* src = g_input_h + ((size_t)(n * H_IN + p + r)) * (W_IN * C_IN);
        uint32_t slotb = sb + SM_IN_OFF + (s & 3) * IN_SLOT;
#pragma unroll
        for (int it = 0; it < 5; it++) {
            int i = it * 256 + tid;              // [0, 1040) chunks
            if (i < IN_ROWS * 8) {
                int row = i >> 3, ch = i & 7;
                uint32_t dst = slotb + row * 128 + ((ch ^ (row & 7)) << 4);
                CP_ASYNC16(dst, src + row * 64 + ch * 8);
            }
        }
    };

    issue_stage(0); CP_COMMIT();   // group also contains the weight loads
    issue_stage(1); CP_COMMIT();
    issue_stage(2); CP_COMMIT();

    float acc[4][4][4];
#pragma unroll
    for (int a = 0; a < 4; a++)
#pragma unroll
        for (int b = 0; b < 4; b++)
#pragma unroll
            for (int c = 0; c < 4; c++) acc[a][b][c] = 0.0f;

    for (int s = 0; s < NSTAGES; s++) {
        const int r = s % 3;

        CP_WAIT2();            // slot s%4 (and, at s=0, the weights) are resident
        __syncthreads();       // also protects slot (s+3)%4 against lagging consumers
        if (s + 3 < NSTAGES) issue_stage(s + 3);
        CP_COMMIT();           // empty groups at the tail keep wait_group arithmetic valid

        const uint32_t islot = sb + SM_IN_OFF + (s & 3) * IN_SLOT;

#pragma unroll
        for (int ss = 0; ss < 3; ss++) {
            const uint32_t wslot = sb + (r * 3 + ss) * W_SLOT;
#pragma unroll
            for (int kk = 0; kk < 4; kk++) {     // 16-deep c chunks
                uint32_t a[4][4];
#pragma unroll
                for (int mf = 0; mf < 4; mf++) { // A = weights [k][c], row-major
                    int row = k0w + 16 * mf + (lane & 15);
                    int ch  = kk * 2 + (lane >> 4);
                    LDSM_X4(a[mf], wslot + row * 128 + ((ch ^ (row & 7)) << 4));
                }
                uint32_t b[2][4];
#pragma unroll
                for (int nh = 0; nh < 2; nh++) {
                    // B = input [q][c] row-major = B^T; fragment wants lane i ->
                    // T[q0+i/4][(i%4)*2+j], which is the NON-trans ldmatrix pattern.
                    int row = q0w + nh * 16 + (lane & 7) + ((lane >> 4) << 3) + ss;
                    int ch  = kk * 2 + ((lane >> 3) & 1);
                    LDSM_X4(b[nh], islot + row * 128 + ((ch ^ (row & 7)) << 4));
                }
#pragma unroll
                for (int mf = 0; mf < 4; mf++)
#pragma unroll
                    for (int nh = 0; nh < 2; nh++) {
                        MMA16816(acc[mf][nh * 2 + 0], a[mf], b[nh][0], b[nh][1]);
                        MMA16816(acc[mf][nh * 2 + 1], a[mf], b[nh][2], b[nh][3]);
                    }
            }
        }

        if (r == 2) {  // tile done: D[k][q] -> out[n][k][p][q], coalesced float2
            int t = (s / 3) * NCTA + blockIdx.x;
            int n = t / P_OUT, p = t - n * P_OUT;
            float* ob = out + (size_t)n * K_OUT * PQ + p * Q_OUT;
            const int lr = lane >> 2, lc = (lane & 3) * 2;
#pragma unroll
            for (int mf = 0; mf < 4; mf++) {
#pragma unroll
                for (int nf = 0; nf < 4; nf++) {
                    int k = k0w + 16 * mf + lr;
                    int q = q0w + 8 * nf + lc;
                    if (q < Q_OUT) {
                        float2 v0 = make_float2(acc[mf][nf][0], acc[mf][nf][1]);
                        float2 v1 = make_float2(acc[mf][nf][2], acc[mf][nf][3]);
                        *(float2*)(ob + (size_t)k * PQ + q)       = v0;
                        *(float2*)(ob + (size_t)(k + 8) * PQ + q) = v1;
                    }
                    acc[mf][nf][0] = acc[mf][nf][1] = acc[mf][nf][2] = acc[mf][nf][3] = 0.0f;
                }
            }
        }
    }
}

// ---------------- host launch ----------------
extern "C" void kernel_launch(void* const* d_in, const int* in_sizes, int n_in,
                              void* d_out, int out_size)
{
    const float* data = (const float*)d_in[0];   // [16,64,128,128] f32
    const float* wts  = (const float*)d_in[1];   // [128,64,3,3]  f32
    float* out        = (float*)d_out;           // [16,128,126,126] f32

    convert_weights_kernel<<<(9 * K_OUT * C_IN + 255) / 256, 256>>>(wts);
    convert_input_kernel<<<dim3(W_IN / 32, H_IN, NB), 256>>>(data);

    static bool attr_set = false;
    if (!attr_set) {
        cudaFuncSetAttribute(conv_mma_kernel,
                             cudaFuncAttributeMaxDynamicSharedMemorySize, SM_TOTAL);
        attr_set = true;
    }
    conv_mma_kernel<<<NCTA, NTHREADS, SM_TOTAL>>>(out);
}